// round 3
// baseline (speedup 1.0000x reference)
#include <cuda_runtime.h>
#include <math_constants.h>

// ---------------------------------------------------------------------------
// Problem: att = softmax( MLP3(concat(node1, u_rep)) ), N = 200000, d = 128.
// Trick:   concat half is constant -> fold u_rep@W1b^T + b1 into cvec[128].
// Work:    2x (N x 128 x 128) fp32 GEMM + dot(W3) + global softmax.
// ---------------------------------------------------------------------------

#define EMB   128
#define TILE  128
#define CAP   262144      // max N supported by scratch
#define NPART 256

// Device scratch (no allocations allowed in kernel_launch)
__device__ float        g_logits[CAP];
__device__ float        g_w1t[EMB * EMB];   // W1a transposed: [k][o]
__device__ float        g_w2t[EMB * EMB];   // W2  transposed: [k][o]
__device__ float        g_cvec[EMB];        // u_rep @ W1b^T + b1
__device__ float        g_partial[NPART];
__device__ unsigned int g_max_u;
__device__ float        g_inv_sum;

// Order-preserving float<->uint encoding for deterministic atomicMax
__device__ __forceinline__ unsigned f2o(float f) {
    unsigned u = __float_as_uint(f);
    return (u & 0x80000000u) ? ~u : (u | 0x80000000u);
}
__device__ __forceinline__ float o2f(unsigned u) {
    return (u & 0x80000000u) ? __uint_as_float(u & 0x7fffffffu)
                             : __uint_as_float(~u);
}

// Packed f32x2 FMA (Blackwell): 2 fp32 FMAs per instruction
#define FMA2(d, a, b) \
    asm("fma.rn.f32x2 %0, %1, %2, %0;" : "+l"(d) : "l"(a), "l"(b))
#define PACKD(d, f) \
    asm("mov.b64 %0, {%1, %1};" : "=l"(d) : "f"(f))
#define UNPACKD(lo, hi, d) \
    asm("mov.b64 {%0, %1}, %2;" : "=f"(lo), "=f"(hi) : "l"(d))

// ---------------------------------------------------------------------------
// Prep: transpose W1a/W2 into [k][o] global scratch, compute cvec, reset max.
// ---------------------------------------------------------------------------
__global__ void k_prep(const float* __restrict__ W1, const float* __restrict__ W2,
                       const float* __restrict__ u_rep, const float* __restrict__ b1)
{
    int t = blockIdx.x * blockDim.x + threadIdx.x;   // 64 * 256 = 16384
    int o = t & 127;
    int k = t >> 7;
    if (t < EMB * EMB) {
        g_w1t[t] = W1[o * 256 + k];   // W1 is [128 out, 256 in]; first half = node1 part
        g_w2t[t] = W2[o * 128 + k];
    }
    if (blockIdx.x == 0) {
        if (threadIdx.x == 0) g_max_u = 0u;          // key for -inf
        if (threadIdx.x < 128) {
            int oo = threadIdx.x;
            float acc = b1[oo];
            const float* w = W1 + oo * 256 + 128;    // u_rep half of W1
            #pragma unroll 8
            for (int kk = 0; kk < 128; kk++) acc += u_rep[kk] * w[kk];
            g_cvec[oo] = acc;
        }
    }
}

// ---------------------------------------------------------------------------
// Core GEMM: C[128x128] += A_t * B_t, both stored k-major with 16B-chunk XOR
// swizzle: elem (k, j) lives at  sm[k*128 + 4*((j>>2) ^ (k&31)) + (j&3)].
// Thread (tx, ty) owns rows r0=ty*8..+7, cols c0=tx*8..+7, accumulators packed
// in pairs of rows: acc[r2*8+c] = (row r0+2*r2, row r0+2*r2+1) at col c0+c.
// ---------------------------------------------------------------------------
__device__ __forceinline__ void gemm128(const float* __restrict__ As,
                                        const float* __restrict__ Bs,
                                        unsigned long long acc[32],
                                        int tx, int ty)
{
    const int ca = ty * 2;
    const int cb = tx * 2;
    #pragma unroll 8
    for (int k = 0; k < 128; k++) {
        const int x = k & 31;
        const ulonglong2* Ak = (const ulonglong2*)(As + k * 128);
        const float4*     Bk = (const float4*)(Bs + k * 128);
        ulonglong2 a0 = Ak[ca ^ x];          // rows r0..r0+3  (2x packed pairs)
        ulonglong2 a1 = Ak[(ca + 1) ^ x];    // rows r0+4..r0+7
        float4     b0 = Bk[cb ^ x];          // cols c0..c0+3
        float4     b1 = Bk[(cb + 1) ^ x];    // cols c0+4..c0+7
        unsigned long long bd[8];
        PACKD(bd[0], b0.x); PACKD(bd[1], b0.y); PACKD(bd[2], b0.z); PACKD(bd[3], b0.w);
        PACKD(bd[4], b1.x); PACKD(bd[5], b1.y); PACKD(bd[6], b1.z); PACKD(bd[7], b1.w);
        #pragma unroll
        for (int c = 0; c < 8; c++) {
            FMA2(acc[c],      a0.x, bd[c]);
            FMA2(acc[8 + c],  a0.y, bd[c]);
            FMA2(acc[16 + c], a1.x, bd[c]);
            FMA2(acc[24 + c], a1.y, bd[c]);
        }
    }
}

// ---------------------------------------------------------------------------
// Main fused kernel: logits for one 128-row tile + block max -> atomicMax
// smem: As (64KB) | Bs1 (64KB) | Bs2 (64KB) | cbs,b2s,w3s,s_arr (4x128) | red
// ---------------------------------------------------------------------------
__global__ __launch_bounds__(256, 1)
void k_mlp(const float* __restrict__ node1, const float* __restrict__ b2g,
           const float* __restrict__ w3g, const float* __restrict__ b3g, int N)
{
    extern __shared__ float sm[];
    float* As    = sm;
    float* Bs1   = sm + 16384;
    float* Bs2   = sm + 32768;
    float* cbs   = sm + 49152;
    float* b2s   = cbs + 128;
    float* w3s   = b2s + 128;
    float* s_arr = w3s + 128;
    float* red   = s_arr + 128;

    const int tid  = threadIdx.x;
    const int tx   = tid & 15;
    const int ty   = tid >> 4;
    const int base = blockIdx.x * TILE;

    if (tid < 128) {
        cbs[tid] = g_cvec[tid];
        b2s[tid] = b2g[tid];
        w3s[tid] = w3g[tid];
    }

    // --- load node1 tile, transpose+swizzle into As[k][row] ---
    {
        const float4* n4 = (const float4*)node1;
        #pragma unroll
        for (int i = tid; i < 4096; i += 256) {
            int row  = i >> 5;
            int k4   = i & 31;
            int grow = base + row;
            float4 v = make_float4(0.f, 0.f, 0.f, 0.f);
            if (grow < N) v = n4[grow * 32 + k4];
            int kb = k4 * 4;
            int rc = row >> 2, rm = row & 3;
            As[(kb + 0) * 128 + 4 * (rc ^ ((kb + 0) & 31)) + rm] = v.x;
            As[(kb + 1) * 128 + 4 * (rc ^ ((kb + 1) & 31)) + rm] = v.y;
            As[(kb + 2) * 128 + 4 * (rc ^ ((kb + 2) & 31)) + rm] = v.z;
            As[(kb + 3) * 128 + 4 * (rc ^ ((kb + 3) & 31)) + rm] = v.w;
        }
    }
    // --- load both weight matrices (already [k][o]) with swizzle ---
    {
        const float4* w1 = (const float4*)g_w1t;
        const float4* w2 = (const float4*)g_w2t;
        float4* B1 = (float4*)Bs1;
        float4* B2 = (float4*)Bs2;
        #pragma unroll
        for (int i = tid; i < 4096; i += 256) {
            int k = i >> 5, ch = i & 31;
            int d = k * 32 + (ch ^ (k & 31));
            B1[d] = w1[i];
            B2[d] = w2[i];
        }
    }
    __syncthreads();

    const int r0 = ty * 8, c0 = tx * 8;

    // ---------------- layer 1 ----------------
    unsigned long long acc[32];
    #pragma unroll
    for (int i = 0; i < 32; i++) acc[i] = 0ull;
    gemm128(As, Bs1, acc, tx, ty);

    __syncthreads();   // everyone done reading As before it becomes h1

    // relu(C + cvec) -> store transposed+swizzled into As (h1_t[c][r])
    #pragma unroll
    for (int c = 0; c < 8; c++) {
        int cf = c0 + c;
        float bias = cbs[cf];
        float v[8];
        #pragma unroll
        for (int r2 = 0; r2 < 4; r2++) {
            float lo, hi;
            UNPACKD(lo, hi, acc[r2 * 8 + c]);
            v[2 * r2]     = fmaxf(lo + bias, 0.f);
            v[2 * r2 + 1] = fmaxf(hi + bias, 0.f);
        }
        float4* Hc = (float4*)(As + cf * 128);
        int xc = cf & 31;
        Hc[(ty * 2) ^ xc]     = make_float4(v[0], v[1], v[2], v[3]);
        Hc[(ty * 2 + 1) ^ xc] = make_float4(v[4], v[5], v[6], v[7]);
    }
    __syncthreads();

    // ---------------- layer 2 ----------------
    #pragma unroll
    for (int i = 0; i < 32; i++) acc[i] = 0ull;
    gemm128(As, Bs2, acc, tx, ty);

    // relu(C + b2), then partial dot with W3 over this thread's 8 columns
    float sp[8];
    #pragma unroll
    for (int i = 0; i < 8; i++) sp[i] = 0.f;
    #pragma unroll
    for (int c = 0; c < 8; c++) {
        int cf = c0 + c;
        float bias = b2s[cf];
        float w3v  = w3s[cf];
        #pragma unroll
        for (int r2 = 0; r2 < 4; r2++) {
            float lo, hi;
            UNPACKD(lo, hi, acc[r2 * 8 + c]);
            sp[2 * r2]     += fmaxf(lo + bias, 0.f) * w3v;
            sp[2 * r2 + 1] += fmaxf(hi + bias, 0.f) * w3v;
        }
    }
    // reduce across the 16 tx-threads sharing these rows (lane bits 0..3)
    #pragma unroll
    for (int m = 1; m < 16; m <<= 1) {
        #pragma unroll
        for (int i = 0; i < 8; i++)
            sp[i] += __shfl_xor_sync(0xffffffffu, sp[i], m);
    }
    if (tx == 0) {
        float b3v = b3g[0];
        #pragma unroll
        for (int i = 0; i < 8; i++) s_arr[r0 + i] = sp[i] + b3v;
    }
    __syncthreads();

    // write logits + block max -> deterministic atomicMax
    float v = -CUDART_INF_F;
    if (tid < 128) {
        int gr = base + tid;
        if (gr < N) { v = s_arr[tid]; g_logits[gr] = v; }
    }
    #pragma unroll
    for (int m = 16; m > 0; m >>= 1)
        v = fmaxf(v, __shfl_xor_sync(0xffffffffu, v, m));
    if ((tid & 31) == 0) red[tid >> 5] = v;
    __syncthreads();
    if (tid == 0) {
        float mx = red[0];
        #pragma unroll
        for (int i = 1; i < 8; i++) mx = fmaxf(mx, red[i]);
        atomicMax(&g_max_u, f2o(mx));
    }
}

// ---------------------------------------------------------------------------
// exp(s - max) in place + deterministic per-block partial sums
// ---------------------------------------------------------------------------
__global__ void k_exp(int N)
{
    __shared__ float red[8];
    const float gmax = o2f(g_max_u);
    float s = 0.f;
    for (int i = blockIdx.x * blockDim.x + threadIdx.x; i < N;
         i += gridDim.x * blockDim.x) {
        float e = __expf(g_logits[i] - gmax);
        g_logits[i] = e;
        s += e;
    }
    #pragma unroll
    for (int m = 16; m > 0; m >>= 1) s += __shfl_xor_sync(0xffffffffu, s, m);
    if ((threadIdx.x & 31) == 0) red[threadIdx.x >> 5] = s;
    __syncthreads();
    if (threadIdx.x == 0) {
        float t = 0.f;
        #pragma unroll
        for (int i = 0; i < 8; i++) t += red[i];
        g_partial[blockIdx.x] = t;
    }
}

__global__ void k_finish()
{
    __shared__ float red[8];
    float s = g_partial[threadIdx.x];   // 256 threads, NPART = 256
    #pragma unroll
    for (int m = 16; m > 0; m >>= 1) s += __shfl_xor_sync(0xffffffffu, s, m);
    if ((threadIdx.x & 31) == 0) red[threadIdx.x >> 5] = s;
    __syncthreads();
    if (threadIdx.x == 0) {
        float t = 0.f;
        #pragma unroll
        for (int i = 0; i < 8; i++) t += red[i];
        g_inv_sum = 1.f / t;
    }
}

__global__ void k_norm(float* __restrict__ out, int N)
{
    const float inv = g_inv_sum;
    int i = blockIdx.x * blockDim.x + threadIdx.x;
    if (i < N) out[i] = g_logits[i] * inv;
}

// ---------------------------------------------------------------------------
extern "C" void kernel_launch(void* const* d_in, const int* in_sizes, int n_in,
                              void* d_out, int out_size)
{
    const float* node1 = (const float*)d_in[0];
    const float* u_rep = (const float*)d_in[1];

    // inputs: node1, u_rep, [num_neighs], W1, b1, W2, b2, W3, b3
    int wi = (n_in >= 9) ? 2 + (n_in - 8) : 2;
    if (in_sizes[wi] != 128 * 256) {            // sanity: find W1 by its size
        for (int i = 2; i + 5 < n_in; i++)
            if (in_sizes[i] == 128 * 256) { wi = i; break; }
    }
    const float* W1 = (const float*)d_in[wi + 0];
    const float* b1 = (const float*)d_in[wi + 1];
    const float* W2 = (const float*)d_in[wi + 2];
    const float* b2 = (const float*)d_in[wi + 3];
    const float* W3 = (const float*)d_in[wi + 4];
    const float* b3 = (const float*)d_in[wi + 5];
    float* out = (float*)d_out;

    const int N = in_sizes[0] / EMB;

    const size_t smem = (size_t)(3 * 16384 + 4 * 128 + 8) * sizeof(float);
    cudaFuncSetAttribute(k_mlp, cudaFuncAttributeMaxDynamicSharedMemorySize,
                         (int)smem);

    k_prep<<<64, 256>>>(W1, W2, u_rep, b1);
    k_mlp<<<(N + TILE - 1) / TILE, 256, smem>>>(node1, b2, W3, b3, N);
    k_exp<<<NPART, 256>>>(N);
    k_finish<<<1, 256>>>();
    k_norm<<<(N + 255) / 256, 256>>>(out, N);
}

// round 6
// speedup vs baseline: 2.4251x; 2.4251x over previous
#include <cuda_runtime.h>
#include <cuda_bf16.h>
#include <math_constants.h>
#include <cstdint>

// ---------------------------------------------------------------------------
// att = softmax( MLP3(concat(node1, u_rep)) ), N = 200000, d = 128.
// u_rep half of layer 1 is constant -> fp32 cvec.
// GEMMs via bf16x3 split on mma.sync (HMMA):  D = Ah*Bh + Al*Bh + Ah*Bl.
// Persistent CTAs; weights resident in smem in fragment-packed layout.
// ---------------------------------------------------------------------------

#define EMB    128
#define TILE   128
#define CAP    262144
#define NPART  256
#define NSM    148

// ---- smem layout (bytes) ----
#define OFF_W1H  0
#define OFF_W1L  32768
#define OFF_W2H  65536
#define OFF_W2L  98304
#define OFF_AH   131072
#define OFF_AL   163840
#define OFF_CVEC 196608
#define OFF_B2   197120
#define OFF_W3   197632
#define OFF_PART 198144
#define OFF_RED  199168
#define SMEM_TOTAL 199232

// ---------------- device scratch ----------------
__device__ float        g_logits[CAP];
__device__ __align__(16) __nv_bfloat16 g_w1h[EMB*EMB];
__device__ __align__(16) __nv_bfloat16 g_w1l[EMB*EMB];
__device__ __align__(16) __nv_bfloat16 g_w2h[EMB*EMB];
__device__ __align__(16) __nv_bfloat16 g_w2l[EMB*EMB];
__device__ float        g_cvec[EMB];
__device__ float        g_partial[NPART];
__device__ unsigned int g_max_u;
__device__ float        g_inv_sum;

// order-preserving float<->uint for deterministic atomicMax
__device__ __forceinline__ unsigned f2o(float f) {
    unsigned u = __float_as_uint(f);
    return (u & 0x80000000u) ? ~u : (u | 0x80000000u);
}
__device__ __forceinline__ float o2f(unsigned u) {
    return (u & 0x80000000u) ? __uint_as_float(u & 0x7fffffffu) : __uint_as_float(~u);
}
__device__ __forceinline__ uint32_t b2u(__nv_bfloat162 h) {
    return *reinterpret_cast<uint32_t*>(&h);
}

// mma.sync m16n8k16 bf16, fp32 accumulate in place (sm_80+ PTX, ok on sm_100)
__device__ __forceinline__ void mma_bf16(float* c, const uint32_t* a,
                                         uint32_t b0, uint32_t b1) {
    asm volatile("mma.sync.aligned.m16n8k16.row.col.f32.bf16.bf16.f32 "
        "{%0,%1,%2,%3}, {%4,%5,%6,%7}, {%8,%9}, {%0,%1,%2,%3};"
        : "+f"(c[0]), "+f"(c[1]), "+f"(c[2]), "+f"(c[3])
        : "r"(a[0]), "r"(a[1]), "r"(a[2]), "r"(a[3]), "r"(b0), "r"(b1));
}

// B-fragment-packed element index (bf16 units): B[n][k] for mma "col" operand.
// Per (ntile,kstep,lane): 8 bytes = {B[2t][g],B[2t+1][g],B[2t+8][g],B[2t+9][g]}
__device__ __forceinline__ int bidx(int n, int k) {
    int nt = n >> 3, g = n & 7, t = (k >> 1) & 3, khi = (k >> 3) & 1, ks = k >> 4;
    return ((nt * 8 + ks) * 32 + g * 4 + t) * 4 + khi * 2 + (k & 1);
}

// ---------------------------------------------------------------------------
// Prep: split W1a/W2 into bf16 hi/lo in fragment-packed layout,
// compute fp32 cvec = u_rep @ W1b^T + b1, reset global max.
// ---------------------------------------------------------------------------
__global__ void k_prep(const float* __restrict__ W1, const float* __restrict__ W2,
                       const float* __restrict__ u_rep, const float* __restrict__ b1)
{
    int i = blockIdx.x * blockDim.x + threadIdx.x;   // 64*256 = 16384
    if (i < EMB * EMB) {
        int n = i >> 7, k = i & 127;
        int idx = bidx(n, k);
        float w1 = W1[n * 256 + k];                  // node1 half of W1
        __nv_bfloat16 h1 = __float2bfloat16(w1);
        g_w1h[idx] = h1;
        g_w1l[idx] = __float2bfloat16(w1 - __bfloat162float(h1));
        float w2 = W2[n * 128 + k];
        __nv_bfloat16 h2 = __float2bfloat16(w2);
        g_w2h[idx] = h2;
        g_w2l[idx] = __float2bfloat16(w2 - __bfloat162float(h2));
    }
    if (blockIdx.x == 0) {
        if (threadIdx.x == 0) g_max_u = 0u;          // encodes -inf
        if (threadIdx.x < 128) {
            int o = threadIdx.x;
            float acc = b1[o];
            const float* w = W1 + o * 256 + 128;     // u_rep half
            #pragma unroll 8
            for (int kk = 0; kk < 128; kk++) acc += u_rep[kk] * w[kk];
            g_cvec[o] = acc;
        }
    }
}

// ---------------------------------------------------------------------------
// One 128x128x128 layer: acc += Ah*Wh + Al*Wh + Ah*Wl  (bf16x3)
// A tiles in fragment-packed layout at OFF_AH/OFF_AL; W at offWH/offWL.
// ---------------------------------------------------------------------------
__device__ __forceinline__ void run_layer(char* smc, int offWH, int offWL,
                                          float acc[2][8][4],
                                          int warpM, int warpN, int lane)
{
    #pragma unroll
    for (int ks = 0; ks < 8; ks++) {
        uint4 ah[2], al[2];
        #pragma unroll
        for (int mt = 0; mt < 2; mt++) {
            int mta  = warpM * 2 + mt;
            int aoff = ((mta * 8 + ks) * 32 + lane) * 16;
            ah[mt] = *(const uint4*)(smc + OFF_AH + aoff);
            al[mt] = *(const uint4*)(smc + OFF_AL + aoff);
        }
        #pragma unroll
        for (int j = 0; j < 8; j++) {
            int ntg  = warpN * 8 + j;
            int boff = ((ntg * 8 + ks) * 32 + lane) * 8;
            uint2 bh = *(const uint2*)(smc + offWH + boff);
            uint2 bl = *(const uint2*)(smc + offWL + boff);
            #pragma unroll
            for (int mt = 0; mt < 2; mt++) {
                mma_bf16(acc[mt][j], (const uint32_t*)&ah[mt], bh.x, bh.y);
                mma_bf16(acc[mt][j], (const uint32_t*)&al[mt], bh.x, bh.y);
                mma_bf16(acc[mt][j], (const uint32_t*)&ah[mt], bl.x, bl.y);
            }
        }
    }
}

// ---------------------------------------------------------------------------
// Persistent MLP kernel.
// ---------------------------------------------------------------------------
__global__ __launch_bounds__(256, 1)
void k_mlp(const float* __restrict__ node1, const float* __restrict__ b2g,
           const float* __restrict__ w3g, const float* __restrict__ b3g,
           int N, int ntiles)
{
    extern __shared__ char smc[];
    const int tid   = threadIdx.x;
    const int wid   = tid >> 5;
    const int lane  = tid & 31;
    const int warpM = wid & 3;      // 4-way M split (32 rows each)
    const int warpN = wid >> 2;     // 2-way N split (64 cols each)
    const int g     = lane >> 2;
    const int t     = lane & 3;

    float* s_cvec = (float*)(smc + OFF_CVEC);
    float* s_b2   = (float*)(smc + OFF_B2);
    float* s_w3   = (float*)(smc + OFF_W3);
    float* s_part = (float*)(smc + OFF_PART);
    float* s_red  = (float*)(smc + OFF_RED);

    // resident weights (fragment-packed) + constants
    for (int i = tid; i < 2048; i += 256) {
        ((uint4*)(smc + OFF_W1H))[i] = ((const uint4*)g_w1h)[i];
        ((uint4*)(smc + OFF_W1L))[i] = ((const uint4*)g_w1l)[i];
        ((uint4*)(smc + OFF_W2H))[i] = ((const uint4*)g_w2h)[i];
        ((uint4*)(smc + OFF_W2L))[i] = ((const uint4*)g_w2l)[i];
    }
    if (tid < 128) {
        s_cvec[tid] = g_cvec[tid];
        s_b2[tid]   = b2g[tid];
        s_w3[tid]   = w3g[tid];
    }
    __syncthreads();

    const float fb3 = b3g[0];
    float runmax = -CUDART_INF_F;
    const float4* n4 = (const float4*)node1;

    for (int tile = blockIdx.x; tile < ntiles; tile += gridDim.x) {
        const int base = tile * TILE;

        // ---- stage node1 tile: split fp32 -> bf16 hi/lo, fragment-packed ----
        #pragma unroll 4
        for (int i = tid; i < 4096; i += 256) {
            int r  = i >> 5;
            int q  = i & 31;                 // float4 index: k = 4q
            int gr = base + r;
            float4 v = make_float4(0.f, 0.f, 0.f, 0.f);
            if (gr < N) v = n4[(size_t)gr * 32 + q];
            __nv_bfloat162 h01 = __floats2bfloat162_rn(v.x, v.y);
            __nv_bfloat162 h23 = __floats2bfloat162_rn(v.z, v.w);
            __nv_bfloat162 l01 = __floats2bfloat162_rn(v.x - __bfloat162float(h01.x),
                                                       v.y - __bfloat162float(h01.y));
            __nv_bfloat162 l23 = __floats2bfloat162_rn(v.z - __bfloat162float(h23.x),
                                                       v.w - __bfloat162float(h23.y));
            int mt = r >> 4, gg = r & 7, half = (r >> 3) & 1;
            int ks = q >> 2, khi = (q >> 1) & 1;
            int t0 = (2 * q) & 3, t1 = (2 * q + 1) & 3;
            int cb = ((mt * 8 + ks) * 32 + gg * 4) * 16 + half * 4 + khi * 8;
            *(uint32_t*)(smc + OFF_AH + cb + t0 * 16) = b2u(h01);
            *(uint32_t*)(smc + OFF_AL + cb + t0 * 16) = b2u(l01);
            *(uint32_t*)(smc + OFF_AH + cb + t1 * 16) = b2u(h23);
            *(uint32_t*)(smc + OFF_AL + cb + t1 * 16) = b2u(l23);
        }
        __syncthreads();

        // ---- layer 1 ----
        float acc[2][8][4];
        #pragma unroll
        for (int mt = 0; mt < 2; mt++)
            #pragma unroll
            for (int j = 0; j < 8; j++)
                #pragma unroll
                for (int e = 0; e < 4; e++) acc[mt][j][e] = 0.f;

        run_layer(smc, OFF_W1H, OFF_W1L, acc, warpM, warpN, lane);
        __syncthreads();   // all warps done reading A before rewriting it

        // epilogue 1: relu(C + cvec) -> bf16 hi/lo back into A tiles (k = col)
        #pragma unroll
        for (int mt = 0; mt < 2; mt++) {
            int mta = warpM * 2 + mt;
            #pragma unroll
            for (int j = 0; j < 8; j++) {
                int ntg  = warpN * 8 + j;
                int col0 = ntg * 8 + t * 2;
                float* c = acc[mt][j];
                float v0 = fmaxf(c[0] + s_cvec[col0],     0.f);
                float v1 = fmaxf(c[1] + s_cvec[col0 + 1], 0.f);
                float v2 = fmaxf(c[2] + s_cvec[col0],     0.f);
                float v3 = fmaxf(c[3] + s_cvec[col0 + 1], 0.f);
                __nv_bfloat162 h01 = __floats2bfloat162_rn(v0, v1);
                __nv_bfloat162 h23 = __floats2bfloat162_rn(v2, v3);
                __nv_bfloat162 l01 = __floats2bfloat162_rn(v0 - __bfloat162float(h01.x),
                                                           v1 - __bfloat162float(h01.y));
                __nv_bfloat162 l23 = __floats2bfloat162_rn(v2 - __bfloat162float(h23.x),
                                                           v3 - __bfloat162float(h23.y));
                int cb = ((mta * 8 + (ntg >> 1)) * 32 + g * 4 + t) * 16 + (ntg & 1) * 8;
                *(uint32_t*)(smc + OFF_AH + cb)     = b2u(h01);   // rows g   (half 0)
                *(uint32_t*)(smc + OFF_AL + cb)     = b2u(l01);
                *(uint32_t*)(smc + OFF_AH + cb + 4) = b2u(h23);   // rows g+8 (half 1)
                *(uint32_t*)(smc + OFF_AL + cb + 4) = b2u(l23);
                c[0] = c[1] = c[2] = c[3] = 0.f;
            }
        }
        __syncthreads();

        // ---- layer 2 ----
        run_layer(smc, OFF_W2H, OFF_W2L, acc, warpM, warpN, lane);

        // epilogue 2: relu(C + b2) dot w3 -> per-row partials
        float sp[2][2] = {{0.f, 0.f}, {0.f, 0.f}};   // [mt][half]
        #pragma unroll
        for (int mt = 0; mt < 2; mt++) {
            #pragma unroll
            for (int j = 0; j < 8; j++) {
                int ntg  = warpN * 8 + j;
                int col0 = ntg * 8 + t * 2;
                float* c = acc[mt][j];
                float w0 = s_w3[col0], w1 = s_w3[col0 + 1];
                float bb0 = s_b2[col0], bb1 = s_b2[col0 + 1];
                sp[mt][0] += fmaxf(c[0] + bb0, 0.f) * w0
                           + fmaxf(c[1] + bb1, 0.f) * w1;
                sp[mt][1] += fmaxf(c[2] + bb0, 0.f) * w0
                           + fmaxf(c[3] + bb1, 0.f) * w1;
            }
        }
        // reduce over the 4 lanes (t) sharing each row
        #pragma unroll
        for (int off = 1; off < 4; off <<= 1) {
            #pragma unroll
            for (int mt = 0; mt < 2; mt++) {
                sp[mt][0] += __shfl_xor_sync(0xffffffffu, sp[mt][0], off);
                sp[mt][1] += __shfl_xor_sync(0xffffffffu, sp[mt][1], off);
            }
        }
        if (t == 0) {
            #pragma unroll
            for (int mt = 0; mt < 2; mt++) {
                int rbase = warpM * 32 + mt * 16;
                s_part[warpN * 128 + rbase + g]     = sp[mt][0];
                s_part[warpN * 128 + rbase + 8 + g] = sp[mt][1];
            }
        }
        __syncthreads();

        if (tid < 128) {
            int gr = base + tid;
            if (gr < N) {
                float lg = s_part[tid] + s_part[128 + tid] + fb3;
                g_logits[gr] = lg;
                runmax = fmaxf(runmax, lg);
            }
        }
        __syncthreads();   // s_part + A tiles free before next iteration
    }

    // ---- one deterministic atomicMax per CTA ----
    float m = runmax;
    #pragma unroll
    for (int s = 16; s > 0; s >>= 1) m = fmaxf(m, __shfl_xor_sync(0xffffffffu, m, s));
    if (lane == 0) s_red[wid] = m;
    __syncthreads();
    if (tid == 0) {
        float mx = s_red[0];
        #pragma unroll
        for (int i = 1; i < 8; i++) mx = fmaxf(mx, s_red[i]);
        atomicMax(&g_max_u, f2o(mx));
    }
}

// ---------------------------------------------------------------------------
// softmax tail: exp(s - max) + deterministic partial sums, then normalize
// ---------------------------------------------------------------------------
__global__ void k_exp(int N)
{
    __shared__ float red[8];
    const float gmax = o2f(g_max_u);
    float s = 0.f;
    for (int i = blockIdx.x * blockDim.x + threadIdx.x; i < N;
         i += gridDim.x * blockDim.x) {
        float e = __expf(g_logits[i] - gmax);
        g_logits[i] = e;
        s += e;
    }
    #pragma unroll
    for (int m = 16; m > 0; m >>= 1) s += __shfl_xor_sync(0xffffffffu, s, m);
    if ((threadIdx.x & 31) == 0) red[threadIdx.x >> 5] = s;
    __syncthreads();
    if (threadIdx.x == 0) {
        float t = 0.f;
        #pragma unroll
        for (int i = 0; i < 8; i++) t += red[i];
        g_partial[blockIdx.x] = t;
    }
}

__global__ void k_finish()
{
    __shared__ float red[8];
    float s = g_partial[threadIdx.x];
    #pragma unroll
    for (int m = 16; m > 0; m >>= 1) s += __shfl_xor_sync(0xffffffffu, s, m);
    if ((threadIdx.x & 31) == 0) red[threadIdx.x >> 5] = s;
    __syncthreads();
    if (threadIdx.x == 0) {
        float t = 0.f;
        #pragma unroll
        for (int i = 0; i < 8; i++) t += red[i];
        g_inv_sum = 1.f / t;
    }
}

__global__ void k_norm(float* __restrict__ out, int N)
{
    const float inv = g_inv_sum;
    int i = blockIdx.x * blockDim.x + threadIdx.x;
    if (i < N) out[i] = g_logits[i] * inv;
}

// ---------------------------------------------------------------------------
extern "C" void kernel_launch(void* const* d_in, const int* in_sizes, int n_in,
                              void* d_out, int out_size)
{
    const float* node1 = (const float*)d_in[0];
    const float* u_rep = (const float*)d_in[1];

    // inputs: node1, u_rep, [num_neighs], W1, b1, W2, b2, W3, b3
    int wi = (n_in >= 9) ? 2 + (n_in - 8) : 2;
    if (in_sizes[wi] != 128 * 256) {
        for (int i = 2; i + 5 < n_in; i++)
            if (in_sizes[i] == 128 * 256) { wi = i; break; }
    }
    const float* W1 = (const float*)d_in[wi + 0];
    const float* b1 = (const float*)d_in[wi + 1];
    const float* W2 = (const float*)d_in[wi + 2];
    const float* b2 = (const float*)d_in[wi + 3];
    const float* W3 = (const float*)d_in[wi + 4];
    const float* b3 = (const float*)d_in[wi + 5];
    float* out = (float*)d_out;

    const int N      = in_sizes[0] / EMB;
    const int ntiles = (N + TILE - 1) / TILE;

    cudaFuncSetAttribute(k_mlp, cudaFuncAttributeMaxDynamicSharedMemorySize,
                         SMEM_TOTAL);

    k_prep<<<64, 256>>>(W1, W2, u_rep, b1);
    int grid = ntiles < NSM ? ntiles : NSM;
    k_mlp<<<grid, 256, SMEM_TOTAL>>>(node1, b2, W3, b3, N, ntiles);
    k_exp<<<NPART, 256>>>(N);
    k_finish<<<1, 256>>>();
    k_norm<<<(N + 255) / 256, 256>>>(out, N);
}

// round 7
// speedup vs baseline: 2.5973x; 1.0710x over previous
#include <cuda_runtime.h>
#include <cuda_bf16.h>
#include <math_constants.h>
#include <cstdint>

// ---------------------------------------------------------------------------
// att = softmax( MLP3(concat(node1, u_rep)) ), N = 200000, d = 128.
// Single fused persistent kernel:
//   - u_rep half of layer 1 folded into fp32 cvec (computed in-kernel)
//   - weights split bf16 hi/lo in-kernel into fragment-packed smem
//   - GEMMs via bf16x3 on mma.sync:  D = Ah*Bh + Al*Bh + Ah*Bl
//   - logits kept in registers; grid-wide barrier; fused softmax + normalize
// ---------------------------------------------------------------------------

#define EMB   128
#define TILE  128
#define LMAX  16      // max tiles per CTA (ceil(1563/148) = 11)
#define GMAX  256

// ---- smem layout (bytes) ----
#define OFF_W1   0        // 64KB: W1 frag-packed, 16B/frag = [bh0 bh1 bl0 bl1]
#define OFF_W2   65536    // 64KB
#define OFF_AH   131072   // 32KB
#define OFF_AL   163840   // 32KB
#define OFF_CVEC 196608
#define OFF_B2   197120
#define OFF_W3   197632
#define OFF_PART 198144   // 1KB (2 x 128 floats)
#define OFF_RED  199168
#define SMEM_TOTAL 199232

// ---------------- device scratch (small; no big buffers needed) -------------
__device__ float        g_ctamax[GMAX];
__device__ float        g_ctasum[GMAX];
__device__ unsigned int g_bar;    // zero-init; reset in-kernel each run
__device__ unsigned int g_done;

__device__ __forceinline__ uint32_t b2u(__nv_bfloat162 h) {
    return *reinterpret_cast<uint32_t*>(&h);
}

// mma.sync m16n8k16 bf16, fp32 accumulate in place (sm_80+ PTX)
__device__ __forceinline__ void mma_bf16(float* c, const uint32_t* a,
                                         uint32_t b0, uint32_t b1) {
    asm volatile("mma.sync.aligned.m16n8k16.row.col.f32.bf16.bf16.f32 "
        "{%0,%1,%2,%3}, {%4,%5,%6,%7}, {%8,%9}, {%0,%1,%2,%3};"
        : "+f"(c[0]), "+f"(c[1]), "+f"(c[2]), "+f"(c[3])
        : "r"(a[0]), "r"(a[1]), "r"(a[2]), "r"(a[3]), "r"(b0), "r"(b1));
}

// Weight fragment address (byte offset of the hi element; lo at +8).
// B[n][k] "col" operand of m16n8k16: lane=(n&7)*4+((k>>1)&3),
// sub = ((k>>3)&1)*2 + (k&1); 16B per (key=((n>>3)*8+(k>>4))*32+lane).
__device__ __forceinline__ int widx_hi(int n, int k) {
    int key = (((n >> 3) * 8 + (k >> 4)) * 32 + (n & 7) * 4 + ((k >> 1) & 3));
    int sub = ((k >> 3) & 1) * 2 + (k & 1);
    return key * 16 + sub * 2;
}

// ---------------------------------------------------------------------------
// One 128x128x128 layer: acc += Ah*Wh + Al*Wh + Ah*Wl  (bf16x3)
// ---------------------------------------------------------------------------
__device__ __forceinline__ void run_layer(char* smc, int offW,
                                          float acc[2][8][4],
                                          int warpM, int warpN, int lane)
{
    #pragma unroll
    for (int ks = 0; ks < 8; ks++) {
        uint4 ah[2], al[2];
        #pragma unroll
        for (int mt = 0; mt < 2; mt++) {
            int mta  = warpM * 2 + mt;
            int aoff = ((mta * 8 + ks) * 32 + lane) * 16;
            ah[mt] = *(const uint4*)(smc + OFF_AH + aoff);
            al[mt] = *(const uint4*)(smc + OFF_AL + aoff);
        }
        #pragma unroll
        for (int j = 0; j < 8; j++) {
            int ntg  = warpN * 8 + j;
            int boff = ((ntg * 8 + ks) * 32 + lane) * 16;
            uint4 b = *(const uint4*)(smc + offW + boff);   // bh.x bh.y bl.x bl.y
            #pragma unroll
            for (int mt = 0; mt < 2; mt++) {
                mma_bf16(acc[mt][j], (const uint32_t*)&ah[mt], b.x, b.y);
                mma_bf16(acc[mt][j], (const uint32_t*)&al[mt], b.x, b.y);
                mma_bf16(acc[mt][j], (const uint32_t*)&ah[mt], b.z, b.w);
            }
        }
    }
}

// prefetch one 128-row node1 tile into registers (16 float4 per thread)
__device__ __forceinline__ void pfetch(const float4* __restrict__ n4, int base,
                                       int N, int wid, int lane, float4 pf[16])
{
    #pragma unroll
    for (int it = 0; it < 16; it++) {
        float4 v = make_float4(0.f, 0.f, 0.f, 0.f);
        if (base >= 0) {
            int gr = base + it * 8 + wid;
            if (gr < N) v = n4[(size_t)gr * 32 + lane];
        }
        pf[it] = v;
    }
}

// ---------------------------------------------------------------------------
__global__ __launch_bounds__(256, 1)
void k_fused(const float* __restrict__ node1, const float* __restrict__ u_rep,
             const float* __restrict__ W1, const float* __restrict__ b1,
             const float* __restrict__ W2, const float* __restrict__ b2g,
             const float* __restrict__ w3g, const float* __restrict__ b3g,
             float* __restrict__ out, int N, int ntiles)
{
    extern __shared__ char smc[];
    const int tid   = threadIdx.x;
    const int wid   = tid >> 5;
    const int lane  = tid & 31;
    const int warpM = wid & 3;
    const int warpN = wid >> 2;
    const int g     = lane >> 2;
    const int t     = lane & 3;
    const int bid   = blockIdx.x;
    const unsigned G = gridDim.x;

    float* s_cvec = (float*)(smc + OFF_CVEC);
    float* s_b2   = (float*)(smc + OFF_B2);
    float* s_w3   = (float*)(smc + OFF_W3);
    float* s_part = (float*)(smc + OFF_PART);
    float* s_red  = (float*)(smc + OFF_RED);

    // ---- in-kernel weight split (bf16 hi/lo), fragment-packed ----
    for (int i = tid; i < EMB * EMB; i += 256) {
        int n = i >> 7, k = i & 127;
        int off = widx_hi(n, k);
        float w1 = W1[n * 256 + k];                   // node1 half of W1
        __nv_bfloat16 h1 = __float2bfloat16(w1);
        *(__nv_bfloat16*)(smc + OFF_W1 + off)     = h1;
        *(__nv_bfloat16*)(smc + OFF_W1 + off + 8) =
            __float2bfloat16(w1 - __bfloat162float(h1));
        float w2 = W2[n * 128 + k];
        __nv_bfloat16 h2 = __float2bfloat16(w2);
        *(__nv_bfloat16*)(smc + OFF_W2 + off)     = h2;
        *(__nv_bfloat16*)(smc + OFF_W2 + off + 8) =
            __float2bfloat16(w2 - __bfloat162float(h2));
    }
    // cvec = u_rep @ W1b^T + b1 (fp32, exact path)
    if (tid < 128) {
        float acc = b1[tid];
        const float* w = W1 + tid * 256 + 128;
        #pragma unroll 8
        for (int kk = 0; kk < 128; kk++) acc += u_rep[kk] * w[kk];
        s_cvec[tid] = acc;
        s_b2[tid]   = b2g[tid];
        s_w3[tid]   = w3g[tid];
    }
    __syncthreads();

    const float fb3 = b3g[0];
    const float4* n4 = (const float4*)node1;

    const int nt = (ntiles > bid) ? (ntiles - 1 - bid) / (int)G + 1 : 0;
    float lg[LMAX];           // per-thread logits (tid<128), local array
    float runmax = -CUDART_INF_F;

    float4 pf[16];
    pfetch(n4, (0 < nt) ? (bid * TILE) : -1, N, wid, lane, pf);

    for (int kt = 0; kt < nt; kt++) {
        const int tile = bid + kt * (int)G;
        const int base = tile * TILE;

        // ---- stage: split prefetched fp32 -> bf16 hi/lo, fragment-packed ----
        #pragma unroll
        for (int it = 0; it < 16; it++) {
            float4 v = pf[it];
            int r = it * 8 + wid;      // row in tile
            int q = lane;              // float4 col index (k = 4q)
            __nv_bfloat162 h01 = __floats2bfloat162_rn(v.x, v.y);
            __nv_bfloat162 h23 = __floats2bfloat162_rn(v.z, v.w);
            __nv_bfloat162 l01 = __floats2bfloat162_rn(v.x - __bfloat162float(h01.x),
                                                       v.y - __bfloat162float(h01.y));
            __nv_bfloat162 l23 = __floats2bfloat162_rn(v.z - __bfloat162float(h23.x),
                                                       v.w - __bfloat162float(h23.y));
            int mt = r >> 4, gg = r & 7, half = (r >> 3) & 1;
            int ks = q >> 2, khi = (q >> 1) & 1;
            int t0 = (2 * q) & 3, t1 = (2 * q + 1) & 3;
            int cb = ((mt * 8 + ks) * 32 + gg * 4) * 16 + half * 4 + khi * 8;
            *(uint32_t*)(smc + OFF_AH + cb + t0 * 16) = b2u(h01);
            *(uint32_t*)(smc + OFF_AL + cb + t0 * 16) = b2u(l01);
            *(uint32_t*)(smc + OFF_AH + cb + t1 * 16) = b2u(h23);
            *(uint32_t*)(smc + OFF_AL + cb + t1 * 16) = b2u(l23);
        }
        __syncthreads();

        // ---- layer 1 ----
        float acc[2][8][4];
        #pragma unroll
        for (int mt = 0; mt < 2; mt++)
            #pragma unroll
            for (int j = 0; j < 8; j++)
                #pragma unroll
                for (int e = 0; e < 4; e++) acc[mt][j][e] = 0.f;

        run_layer(smc, OFF_W1, acc, warpM, warpN, lane);
        __syncthreads();                 // A consumed; may be rewritten

        // prefetch next tile while epilogue1 + layer2 run
        {
            int tile2 = bid + (kt + 1) * (int)G;
            pfetch(n4, (tile2 < ntiles) ? tile2 * TILE : -1, N, wid, lane, pf);
        }

        // ---- epilogue 1: relu(C + cvec) -> bf16 hi/lo back into A tiles ----
        #pragma unroll
        for (int mt = 0; mt < 2; mt++) {
            int mta = warpM * 2 + mt;
            #pragma unroll
            for (int j = 0; j < 8; j++) {
                int ntg  = warpN * 8 + j;
                int col0 = ntg * 8 + t * 2;
                float* c = acc[mt][j];
                float v0 = fmaxf(c[0] + s_cvec[col0],     0.f);
                float v1 = fmaxf(c[1] + s_cvec[col0 + 1], 0.f);
                float v2 = fmaxf(c[2] + s_cvec[col0],     0.f);
                float v3 = fmaxf(c[3] + s_cvec[col0 + 1], 0.f);
                __nv_bfloat162 h01 = __floats2bfloat162_rn(v0, v1);
                __nv_bfloat162 h23 = __floats2bfloat162_rn(v2, v3);
                __nv_bfloat162 l01 = __floats2bfloat162_rn(v0 - __bfloat162float(h01.x),
                                                           v1 - __bfloat162float(h01.y));
                __nv_bfloat162 l23 = __floats2bfloat162_rn(v2 - __bfloat162float(h23.x),
                                                           v3 - __bfloat162float(h23.y));
                int cb = ((mta * 8 + (ntg >> 1)) * 32 + g * 4 + t) * 16 + (ntg & 1) * 8;
                *(uint32_t*)(smc + OFF_AH + cb)     = b2u(h01);
                *(uint32_t*)(smc + OFF_AL + cb)     = b2u(l01);
                *(uint32_t*)(smc + OFF_AH + cb + 4) = b2u(h23);
                *(uint32_t*)(smc + OFF_AL + cb + 4) = b2u(l23);
                c[0] = c[1] = c[2] = c[3] = 0.f;
            }
        }
        __syncthreads();

        // ---- layer 2 ----
        run_layer(smc, OFF_W2, acc, warpM, warpN, lane);

        // ---- epilogue 2: relu(C + b2) dot w3 -> per-row partials ----
        float sp[2][2] = {{0.f, 0.f}, {0.f, 0.f}};
        #pragma unroll
        for (int mt = 0; mt < 2; mt++) {
            #pragma unroll
            for (int j = 0; j < 8; j++) {
                int ntg  = warpN * 8 + j;
                int col0 = ntg * 8 + t * 2;
                float* c = acc[mt][j];
                float w0 = s_w3[col0], w1 = s_w3[col0 + 1];
                float bb0 = s_b2[col0], bb1 = s_b2[col0 + 1];
                sp[mt][0] += fmaxf(c[0] + bb0, 0.f) * w0
                           + fmaxf(c[1] + bb1, 0.f) * w1;
                sp[mt][1] += fmaxf(c[2] + bb0, 0.f) * w0
                           + fmaxf(c[3] + bb1, 0.f) * w1;
            }
        }
        #pragma unroll
        for (int off = 1; off < 4; off <<= 1) {
            #pragma unroll
            for (int mt = 0; mt < 2; mt++) {
                sp[mt][0] += __shfl_xor_sync(0xffffffffu, sp[mt][0], off);
                sp[mt][1] += __shfl_xor_sync(0xffffffffu, sp[mt][1], off);
            }
        }
        if (t == 0) {
            #pragma unroll
            for (int mt = 0; mt < 2; mt++) {
                int rbase = warpM * 32 + mt * 16;
                s_part[warpN * 128 + rbase + g]     = sp[mt][0];
                s_part[warpN * 128 + rbase + 8 + g] = sp[mt][1];
            }
        }
        __syncthreads();

        if (tid < 128) {
            int gr = base + tid;
            float v = s_part[tid] + s_part[128 + tid] + fb3;
            lg[kt] = v;
            if (gr < N) runmax = fmaxf(runmax, v);
        }
        __syncthreads();
    }

    // ---- phase-1 end: per-CTA max ----
    float m = runmax;
    #pragma unroll
    for (int s = 16; s > 0; s >>= 1) m = fmaxf(m, __shfl_xor_sync(0xffffffffu, m, s));
    if (lane == 0) s_red[wid] = m;
    __syncthreads();
    if (tid == 0) {
        float mx = s_red[0];
        #pragma unroll
        for (int i = 1; i < 8; i++) mx = fmaxf(mx, s_red[i]);
        g_ctamax[bid] = mx;
        __threadfence();
        atomicAdd(&g_bar, 1u);
        while (atomicAdd(&g_bar, 0u) < G) __nanosleep(64);
        __threadfence();
    }
    __syncthreads();

    // ---- phase 2: global max (deterministic serial), exp, per-CTA sum ----
    float gmax = g_ctamax[0];
    for (unsigned i = 1; i < G; i++) gmax = fmaxf(gmax, g_ctamax[i]);

    float psum = 0.f;
    if (tid < 128) {
        for (int kt = 0; kt < nt; kt++) {
            int gr = (bid + kt * (int)G) * TILE + tid;
            if (gr < N) {
                float e = __expf(lg[kt] - gmax);
                lg[kt] = e;
                psum += e;
            }
        }
    }
    #pragma unroll
    for (int s = 16; s > 0; s >>= 1) psum += __shfl_xor_sync(0xffffffffu, psum, s);
    if (lane == 0) s_red[wid] = psum;
    __syncthreads();
    if (tid == 0) {
        float sm = 0.f;
        #pragma unroll
        for (int i = 0; i < 8; i++) sm += s_red[i];
        g_ctasum[bid] = sm;
        __threadfence();
        atomicAdd(&g_bar, 1u);
        while (atomicAdd(&g_bar, 0u) < 2u * G) __nanosleep(64);
        __threadfence();
    }
    __syncthreads();

    // ---- phase 3: total sum (deterministic serial), normalize, write ----
    float tot = 0.f;
    for (unsigned i = 0; i < G; i++) tot += g_ctasum[i];
    const float inv = 1.f / tot;

    if (tid < 128) {
        for (int kt = 0; kt < nt; kt++) {
            int gr = (bid + kt * (int)G) * TILE + tid;
            if (gr < N) out[gr] = lg[kt] * inv;
        }
    }

    // ---- reset barrier state for next graph replay ----
    __syncthreads();
    if (tid == 0) {
        unsigned d = atomicAdd(&g_done, 1u);
        if (d == G - 1u) {
            atomicExch(&g_bar, 0u);
            atomicExch(&g_done, 0u);
            __threadfence();
        }
    }
}

// ---------------------------------------------------------------------------
extern "C" void kernel_launch(void* const* d_in, const int* in_sizes, int n_in,
                              void* d_out, int out_size)
{
    const float* node1 = (const float*)d_in[0];
    const float* u_rep = (const float*)d_in[1];

    // inputs: node1, u_rep, [num_neighs], W1, b1, W2, b2, W3, b3
    int wi = (n_in >= 9) ? 2 + (n_in - 8) : 2;
    if (in_sizes[wi] != 128 * 256) {
        for (int i = 2; i + 5 < n_in; i++)
            if (in_sizes[i] == 128 * 256) { wi = i; break; }
    }
    const float* W1 = (const float*)d_in[wi + 0];
    const float* b1 = (const float*)d_in[wi + 1];
    const float* W2 = (const float*)d_in[wi + 2];
    const float* b2 = (const float*)d_in[wi + 3];
    const float* W3 = (const float*)d_in[wi + 4];
    const float* b3 = (const float*)d_in[wi + 5];
    float* out = (float*)d_out;

    const int N      = in_sizes[0] / EMB;
    const int ntiles = (N + TILE - 1) / TILE;

    int nsm = 0;
    cudaDeviceGetAttribute(&nsm, cudaDevAttrMultiProcessorCount, 0);
    if (nsm <= 0) nsm = 148;
    int grid = ntiles < nsm ? ntiles : nsm;
    if (grid > GMAX) grid = GMAX;

    cudaFuncSetAttribute(k_fused, cudaFuncAttributeMaxDynamicSharedMemorySize,
                         SMEM_TOTAL);
    k_fused<<<grid, 256, SMEM_TOTAL>>>(node1, u_rep, W1, b1, W2, b2, W3, b3,
                                       out, N, ntiles);
}